// round 4
// baseline (speedup 1.0000x reference)
#include <cuda_runtime.h>
#include <cstdint>
#include <cstddef>

// ---------------------------------------------------------------------------
// 2-layer LSTM, B=32, T=512, I=H=1024, fp32.
// out = [outputs (32*512*1024)] [h_n (2*32*1024)] [c_n (2*32*1024)]
//
// Persistent kernel, 128 CTAs x 256 threads, one CTA per SM (forced by ~196KB
// dynamic smem), global sense-reversing barrier between the 1024 layer-steps.
// Per phase each CTA computes 8 neurons x 4 gates x 32 batches (k = 2048 dot
// products): warp = 4 gate rows, lane = batch, MACs via packed fma.rn.f32x2,
// W streamed through smem (broadcast LDS), activations in a swizzled smem
// tile, c-state in registers for all 512 steps.
// ---------------------------------------------------------------------------

#define NCTA   128
#define NTHR   256
#define TSTEPS 512
#define HDIM   1024

// h ping-pong buffers: [layer][pp][b*1024+n]
__device__ float g_h[2 * 2 * 32 * HDIM];
__device__ unsigned g_bar_count;
__device__ volatile unsigned g_bar_gen;

union F2 { unsigned long long u; float2 f; };

__device__ __forceinline__ void ffma2(unsigned long long& acc,
                                      unsigned long long a,
                                      unsigned long long b) {
    asm volatile("fma.rn.f32x2 %0, %1, %2, %0;" : "+l"(acc) : "l"(a), "l"(b));
}

__device__ __forceinline__ void grid_bar() {
    __syncthreads();
    if (threadIdx.x == 0) {
        __threadfence();                       // release: h writes visible
        unsigned gen = g_bar_gen;
        if (atomicAdd(&g_bar_count, 1u) == NCTA - 1) {
            g_bar_count = 0;
            __threadfence();
            g_bar_gen = gen + 1;               // release all
        } else {
            while (g_bar_gen == gen) { __nanosleep(32); }
        }
        __threadfence();                       // acquire
    }
    __syncthreads();
}

extern "C" __global__ void __launch_bounds__(NTHR, 1)
lstm_persist(const float* __restrict__ x,
             const float* __restrict__ W0, const float* __restrict__ b0,
             const float* __restrict__ W1, const float* __restrict__ b1,
             float* __restrict__ out)
{
    extern __shared__ float smem[];
    float* comb = smem;                 // [32][1024] activations (swizzled)
    float* Ws   = smem + 32768;         // [32][512] weight chunk
    float* gs   = smem + 49152;         // [32][33] gate results

    const int tid  = threadIdx.x;
    const int cta  = blockIdx.x;
    const int w    = tid >> 5;          // GEMM: warp -> local rows 4w..4w+3
    const int lane = tid & 31;          // GEMM: lane -> batch
    const int j    = tid & 7;           // pointwise: neuron within CTA
    const int bb   = tid >> 3;          // pointwise: batch
    const int ng   = cta * 8 + j;       // global neuron index

    // zero the h state buffers (both ping-pong slots)
    {
        int base = cta * 1024 + tid;
        #pragma unroll
        for (int k = 0; k < 4; k++) g_h[base + k * 256] = 0.f;
    }

    // per-thread biases: gate order f,i,g,o -> rows g*1024 + ng
    float br[2][4];
    #pragma unroll
    for (int g = 0; g < 4; ++g) {
        br[0][g] = b0[g * HDIM + ng];
        br[1][g] = b1[g * HDIM + ng];
    }
    float cst[2] = {0.f, 0.f};          // cell state, registers across all t

    grid_bar();                          // h buffers zeroed everywhere

    for (int t = 0; t < TSTEPS; ++t) {
        const int pp = t & 1;
        #pragma unroll 1
        for (int l = 0; l < 2; ++l) {
            const float* Wm = l ? W1 : W0;
            unsigned long long acc0 = 0, acc1 = 0, acc2 = 0, acc3 = 0;

            #pragma unroll 1
            for (int half = 0; half < 2; ++half) {
                // ---- stage comb[32][1024] (swizzled float4 layout) ----
                if (l == 0 && half == 0) {
                    // x_t : x[b][t][k]
                    const float4* src = (const float4*)x;
                    #pragma unroll
                    for (int i = 0; i < 32; i++) {
                        int flat = i * 256 + tid;
                        int b = flat >> 8, kq = flat & 255;
                        float4 v = __ldg(&src[(size_t)b * 131072 + (size_t)t * 256 + kq]);
                        *(float4*)&comb[(b * 256 + (kq ^ (b & 7))) << 2] = v;
                    }
                } else {
                    // half0 (l==1): layer0 output this step; half1: own h_prev
                    int lsrc = (half == 0) ? 0 : l;
                    int psrc = (half == 0) ? pp : (1 - pp);
                    const float4* src = (const float4*)&g_h[(lsrc * 2 + psrc) * 32768];
                    #pragma unroll
                    for (int i = 0; i < 32; i++) {
                        int flat = i * 256 + tid;
                        int b = flat >> 8, kq = flat & 255;
                        float4 v = __ldcg(&src[flat]);   // L2, never stale L1
                        *(float4*)&comb[(b * 256 + (kq ^ (b & 7))) << 2] = v;
                    }
                }
                __syncthreads();

                #pragma unroll 1
                for (int chunk = 0; chunk < 2; ++chunk) {
                    const int kbase = half * 1024 + chunk * 512;
                    // ---- stage Ws[32][512]: warp stages its 4 rows ----
                    #pragma unroll
                    for (int rr = 0; rr < 4; ++rr) {
                        int r    = 4 * w + rr;                       // local row
                        int grow = (r >> 3) * HDIM + cta * 8 + (r & 7); // W row
                        const float4* wsrc =
                            (const float4*)(Wm + (size_t)grow * 2048 + kbase);
                        float4* wdst = (float4*)(Ws + r * 512);
                        #pragma unroll
                        for (int i2 = 0; i2 < 4; i2++)
                            wdst[lane + 32 * i2] = __ldg(&wsrc[lane + 32 * i2]);
                    }
                    __syncthreads();

                    const float* wr0 = Ws + (4 * w + 0) * 512;
                    const float* wr1 = Ws + (4 * w + 1) * 512;
                    const float* wr2 = Ws + (4 * w + 2) * 512;
                    const float* wr3 = Ws + (4 * w + 3) * 512;
                    #pragma unroll 4
                    for (int kq = 0; kq < 128; ++kq) {
                        int kt = chunk * 128 + kq;
                        ulonglong2 cv =
                            *(const ulonglong2*)&comb[(lane * 256 + (kt ^ (lane & 7))) << 2];
                        ulonglong2 w0v = *(const ulonglong2*)&wr0[kq << 2];
                        ulonglong2 w1v = *(const ulonglong2*)&wr1[kq << 2];
                        ulonglong2 w2v = *(const ulonglong2*)&wr2[kq << 2];
                        ulonglong2 w3v = *(const ulonglong2*)&wr3[kq << 2];
                        ffma2(acc0, w0v.x, cv.x);  ffma2(acc0, w0v.y, cv.y);
                        ffma2(acc1, w1v.x, cv.x);  ffma2(acc1, w1v.y, cv.y);
                        ffma2(acc2, w2v.x, cv.x);  ffma2(acc2, w2v.y, cv.y);
                        ffma2(acc3, w3v.x, cv.x);  ffma2(acc3, w3v.y, cv.y);
                    }
                    __syncthreads();
                }
            }

            // ---- fold f32x2 halves, publish gates to smem ----
            {
                F2 u;
                u.u = acc0; gs[(4 * w + 0) * 33 + lane] = u.f.x + u.f.y;
                u.u = acc1; gs[(4 * w + 1) * 33 + lane] = u.f.x + u.f.y;
                u.u = acc2; gs[(4 * w + 2) * 33 + lane] = u.f.x + u.f.y;
                u.u = acc3; gs[(4 * w + 3) * 33 + lane] = u.f.x + u.f.y;
            }
            __syncthreads();

            // ---- pointwise: thread owns (neuron j, batch bb) ----
            float fg = gs[(0  + j) * 33 + bb] + br[l][0];
            float ig = gs[(8  + j) * 33 + bb] + br[l][1];
            float gg = gs[(16 + j) * 33 + bb] + br[l][2];
            float og = gs[(24 + j) * 33 + bb] + br[l][3];
            fg = 1.f / (1.f + expf(-fg));
            ig = 1.f / (1.f + expf(-ig));
            og = 1.f / (1.f + expf(-og));
            float c = fg * cst[l] + ig * tanhf(gg);
            cst[l] = c;
            float h = og * tanhf(c);

            g_h[(l * 2 + pp) * 32768 + bb * HDIM + ng] = h;
            if (l == 1)
                out[(size_t)bb * 524288 + (size_t)t * 1024 + ng] = h;
            if (t == TSTEPS - 1) {
                out[16777216 + l * 32768 + bb * 1024 + ng] = h;   // h_n
                out[16842752 + l * 32768 + bb * 1024 + ng] = c;   // c_n
            }

            grid_bar();
        }
    }
}

extern "C" void kernel_launch(void* const* d_in, const int* in_sizes, int n_in,
                              void* d_out, int out_size)
{
    (void)in_sizes; (void)n_in; (void)out_size;
    const float* x  = (const float*)d_in[0];
    const float* W0 = (const float*)d_in[1];
    const float* b0 = (const float*)d_in[2];
    const float* W1 = (const float*)d_in[3];
    const float* b1 = (const float*)d_in[4];

    const int smem_bytes = (32768 + 16384 + 32 * 33) * 4;   // 200832
    cudaFuncSetAttribute(lstm_persist,
                         cudaFuncAttributeMaxDynamicSharedMemorySize, smem_bytes);
    lstm_persist<<<NCTA, NTHR, smem_bytes>>>(x, W0, b0, W1, b1, (float*)d_out);
}

// round 5
// speedup vs baseline: 1.3175x; 1.3175x over previous
#include <cuda_runtime.h>
#include <cstdint>
#include <cstddef>

// ---------------------------------------------------------------------------
// 2-layer LSTM, B=32, T=512, I=H=1024, fp32.
// out = [outputs (32*512*1024)] [h_n (2*32*1024)] [c_n (2*32*1024)]
//
// Persistent kernel, 128 CTAs x 256 threads, 1 CTA/SM (forced by smem),
// global sense-reversing barrier between the 1024 layer-steps.
// Per phase each CTA computes 32 gate-rows x 32 batches x k=2048:
//  - 8 k-stages of 256, cp.async double-buffered (W + comb ping-pong)
//  - warp = 8 rows x 32 b x k-half; lane grid 4 r-lanes x 8 b-lanes;
//    thread tile 2 rows x 4 batches, 16 FFMA2 per 6 LDS.128 (swizzled,
//    conflict-free)
//  - weights pre-rearranged once into per-(cta,stage) contiguous swizzled
//    blocks so staging is pure contiguous cp.async
//  - c-state in registers across all 512 steps
// ---------------------------------------------------------------------------

#define NCTA   128
#define NTHR   256
#define TSTEPS 512
#define HDIM   1024

#define OFF_W   0u        // 2 x 32KB weight stage buffers
#define OFF_C   65536u    // 2 x 32KB comb stage buffers
#define OFF_GS  131072u   // 32x33 floats gate results
#define SMEM_BYTES 135296

// rearranged weights: [l][cta][stage][2048 chunks of 16B] (swizzled)
__device__ __align__(16) float g_Wre[2u * 128u * 8u * 2048u * 4u];
// h ping-pong: [layer][pp][b*1024+n]
__device__ __align__(16) float g_h[2 * 2 * 32 * HDIM];
__device__ unsigned g_bar_count;
__device__ volatile unsigned g_bar_gen;

union F2 { unsigned long long u; float2 f; };

__device__ __forceinline__ void ffma2(unsigned long long& acc,
                                      unsigned long long a,
                                      unsigned long long b) {
    asm volatile("fma.rn.f32x2 %0, %1, %2, %0;" : "+l"(acc) : "l"(a), "l"(b));
}
__device__ __forceinline__ void cpa16(uint32_t dst, const void* src) {
    asm volatile("cp.async.cg.shared.global [%0], [%1], 16;" :: "r"(dst), "l"(src));
}
__device__ __forceinline__ void cp_commit() {
    asm volatile("cp.async.commit_group;");
}
template<int N> __device__ __forceinline__ void cp_wait() {
    asm volatile("cp.async.wait_group %0;" :: "n"(N));
}

__device__ __forceinline__ void grid_bar() {
    __syncthreads();
    if (threadIdx.x == 0) {
        __threadfence();
        unsigned gen = g_bar_gen;
        if (atomicAdd(&g_bar_count, 1u) == NCTA - 1) {
            g_bar_count = 0;
            __threadfence();
            g_bar_gen = gen + 1;
        } else {
            while (g_bar_gen == gen) { __nanosleep(32); }
        }
        __threadfence();
    }
    __syncthreads();
}

// stage weights: contiguous pre-swizzled block -> smem buffer
__device__ __forceinline__ void fetch_W(uint32_t sb, uint32_t dstoff,
                                        int l, int s, int cta, int tid) {
    const float4* src = ((const float4*)g_Wre) +
                        (((size_t)l * 128 + cta) * 8 + s) * 2048;
    uint32_t d = sb + dstoff;
    #pragma unroll
    for (int i = 0; i < 8; i++) {
        int m = tid + i * 256;
        cpa16(d + m * 16, src + m);
    }
}

// stage activations: comb[b][256k] rows with blane swizzle
__device__ __forceinline__ void fetch_C(uint32_t sb, uint32_t dstoff,
                                        const float* base, size_t stride,
                                        int tid) {
    uint32_t d = sb + dstoff;
    #pragma unroll
    for (int i = 0; i < 8; i++) {
        int m = tid + i * 256;
        int b = m >> 6, c = m & 63;
        cpa16(d + (((b << 6) + (c ^ (b >> 2))) << 4),
              base + (size_t)b * stride + (c << 2));
    }
}

// source pointer for comb stage s of phase (t, l)
__device__ __forceinline__ const float* comb_src(const float* x, int t, int l,
                                                 int pp, int s, size_t* stride) {
    if (l == 0) {
        if (s < 4) { *stride = 524288; return x + (size_t)t * 1024 + s * 256; }
        *stride = 1024; return g_h + (0 * 2 + (1 - pp)) * 32768 + (s - 4) * 256;
    } else {
        *stride = 1024;
        if (s < 4) return g_h + (0 * 2 + pp) * 32768 + s * 256;
        return g_h + (2 + (1 - pp)) * 32768 + (s - 4) * 256;
    }
}

// one-time weight rearrangement into swizzled per-(cta,stage) blocks
extern "C" __global__ void lstm_rearrange(const float* __restrict__ W0,
                                          const float* __restrict__ W1) {
    unsigned gid = blockIdx.x * 256u + threadIdx.x;
    #pragma unroll
    for (int i = 0; i < 4; i++) {
        unsigned m = gid + (unsigned)i * 1048576u;
        unsigned l    = m >> 21;
        unsigned rest = m & 2097151u;
        unsigned cta  = rest >> 14;
        unsigned r2   = rest & 16383u;
        unsigned s    = r2 >> 11;
        unsigned mm   = r2 & 2047u;
        unsigned r    = mm >> 6;
        unsigned cp   = mm & 63u;
        unsigned c    = cp ^ (r & 7u);               // store swizzled
        unsigned gr   = (r >> 3) * 1024u + cta * 8u + (r & 7u);
        const float* W = l ? W1 : W0;
        const float4* src = (const float4*)(W + (size_t)gr * 2048 + s * 256 + c * 4);
        ((float4*)g_Wre)[m] = *src;
    }
}

extern "C" __global__ void __launch_bounds__(NTHR, 1)
lstm_persist(const float* __restrict__ x,
             const float* __restrict__ b0,
             const float* __restrict__ b1,
             float* __restrict__ out)
{
    extern __shared__ char sm[];
    const uint32_t sb = (uint32_t)__cvta_generic_to_shared(sm);
    float* gs = (float*)(sm + OFF_GS);

    const int tid  = threadIdx.x;
    const int cta  = blockIdx.x;
    const int w    = tid >> 5;
    const int lane = tid & 31;
    const int khalf  = w >> 2;          // 0/1: k-half within stage
    const int rblock = w & 3;           // 4 row-blocks of 8 rows
    const int rlane  = lane >> 3;       // 0..3
    const int blane  = lane & 7;        // 0..7
    const int r0  = rblock * 8 + rlane * 2;
    const int sw0 = rlane * 2, sw1 = rlane * 2 + 1;
    // pointwise mapping
    const int pj = tid & 7;             // neuron within CTA
    const int pb = tid >> 3;            // batch
    const int ng = cta * 8 + pj;

    // zero h state (all 4 buffers, 131072 floats total across 128 CTAs)
    {
        int base = cta * 1024 + tid;
        #pragma unroll
        for (int k = 0; k < 4; k++) g_h[base + k * 256] = 0.f;
    }
    float br[2][4];
    #pragma unroll
    for (int g = 0; g < 4; ++g) {
        br[0][g] = b0[g * HDIM + ng];
        br[1][g] = b1[g * HDIM + ng];
    }
    float cst[2] = {0.f, 0.f};

    grid_bar();

    for (int t = 0; t < TSTEPS; ++t) {
        const int pp = t & 1;
        #pragma unroll 1
        for (int l = 0; l < 2; ++l) {
            // ---- ensure stage 0 resident (most was prefetched pre-barrier) ----
            const bool haveW0 = !(t == 0 && l == 0);
            const bool haveC0 = (l == 0 && t > 0);
            if (!haveW0 || !haveC0) {
                if (!haveW0) fetch_W(sb, OFF_W, l, 0, cta, tid);
                if (!haveC0) {
                    size_t str; const float* src = comb_src(x, t, l, pp, 0, &str);
                    fetch_C(sb, OFF_C, src, str, tid);
                }
                cp_commit();
            }

            unsigned long long acc[16];
            #pragma unroll
            for (int i = 0; i < 16; i++) acc[i] = 0ull;

            #pragma unroll 1
            for (int s = 0; s < 8; ++s) {
                if (s < 7) {
                    uint32_t boff = (uint32_t)(((s + 1) & 1) << 15);
                    fetch_W(sb, OFF_W + boff, l, s + 1, cta, tid);
                    size_t str; const float* src = comb_src(x, t, l, pp, s + 1, &str);
                    fetch_C(sb, OFF_C + boff, src, str, tid);
                    cp_commit();
                    cp_wait<1>();
                } else {
                    cp_wait<0>();
                }
                __syncthreads();

                const char* Wp0 = sm + ((s & 1) << 15) + r0 * 1024;
                const char* Wp1 = Wp0 + 1024;
                const char* Cp0 = sm + OFF_C + ((s & 1) << 15) + blane * 4096;
                const int kq0 = khalf * 32;
                #pragma unroll 4
                for (int kq = kq0; kq < kq0 + 32; ++kq) {
                    const int co = ((kq) ^ blane) << 4;
                    ulonglong2 cv0 = *(const ulonglong2*)(Cp0 + co);
                    ulonglong2 cv1 = *(const ulonglong2*)(Cp0 + co + 1024);
                    ulonglong2 cv2 = *(const ulonglong2*)(Cp0 + co + 2048);
                    ulonglong2 cv3 = *(const ulonglong2*)(Cp0 + co + 3072);
                    ulonglong2 wv0 = *(const ulonglong2*)(Wp0 + ((kq ^ sw0) << 4));
                    ulonglong2 wv1 = *(const ulonglong2*)(Wp1 + ((kq ^ sw1) << 4));
                    ffma2(acc[0],  wv0.x, cv0.x);  ffma2(acc[1],  wv0.y, cv0.y);
                    ffma2(acc[2],  wv0.x, cv1.x);  ffma2(acc[3],  wv0.y, cv1.y);
                    ffma2(acc[4],  wv0.x, cv2.x);  ffma2(acc[5],  wv0.y, cv2.y);
                    ffma2(acc[6],  wv0.x, cv3.x);  ffma2(acc[7],  wv0.y, cv3.y);
                    ffma2(acc[8],  wv1.x, cv0.x);  ffma2(acc[9],  wv1.y, cv0.y);
                    ffma2(acc[10], wv1.x, cv1.x);  ffma2(acc[11], wv1.y, cv1.y);
                    ffma2(acc[12], wv1.x, cv2.x);  ffma2(acc[13], wv1.y, cv2.y);
                    ffma2(acc[14], wv1.x, cv3.x);  ffma2(acc[15], wv1.y, cv3.y);
                }
                __syncthreads();
            }

            // ---- k-split reduction into gs[32][33] ----
            if (khalf == 0) {
                #pragma unroll
                for (int rr = 0; rr < 2; rr++)
                    #pragma unroll
                    for (int bt = 0; bt < 4; bt++) {
                        F2 u0, u1;
                        u0.u = acc[rr * 8 + bt * 2 + 0];
                        u1.u = acc[rr * 8 + bt * 2 + 1];
                        gs[(r0 + rr) * 33 + blane * 4 + bt] =
                            u0.f.x + u0.f.y + u1.f.x + u1.f.y;
                    }
            }
            __syncthreads();
            if (khalf == 1) {
                #pragma unroll
                for (int rr = 0; rr < 2; rr++)
                    #pragma unroll
                    for (int bt = 0; bt < 4; bt++) {
                        F2 u0, u1;
                        u0.u = acc[rr * 8 + bt * 2 + 0];
                        u1.u = acc[rr * 8 + bt * 2 + 1];
                        gs[(r0 + rr) * 33 + blane * 4 + bt] +=
                            u0.f.x + u0.f.y + u1.f.x + u1.f.y;
                    }
            }
            __syncthreads();

            // ---- pointwise: thread owns (neuron pj, batch pb) ----
            float fg = gs[(0  + pj) * 33 + pb] + br[l][0];
            float ig = gs[(8  + pj) * 33 + pb] + br[l][1];
            float gg = gs[(16 + pj) * 33 + pb] + br[l][2];
            float og = gs[(24 + pj) * 33 + pb] + br[l][3];
            fg = 1.f / (1.f + expf(-fg));
            ig = 1.f / (1.f + expf(-ig));
            og = 1.f / (1.f + expf(-og));
            float c = fg * cst[l] + ig * tanhf(gg);
            cst[l] = c;
            float h = og * tanhf(c);

            g_h[(l * 2 + pp) * 32768 + pb * HDIM + ng] = h;
            if (l == 1)
                out[(size_t)pb * 524288 + (size_t)t * 1024 + ng] = h;
            if (t == TSTEPS - 1) {
                out[16777216 + l * 32768 + pb * 1024 + ng] = h;   // h_n
                out[16842752 + l * 32768 + pb * 1024 + ng] = c;   // c_n
            }

            // ---- prefetch next phase's stage 0 before the barrier ----
            const bool lastPhase = (t == TSTEPS - 1) && (l == 1);
            if (!lastPhase) {
                const int nl = l ^ 1;
                fetch_W(sb, OFF_W, nl, 0, cta, tid);          // always safe
                if (l == 1) {                                  // next is (t+1, l=0): x
                    fetch_C(sb, OFF_C, x + (size_t)(t + 1) * 1024, 524288, tid);
                }
                cp_commit();
            }

            grid_bar();
        }
    }
}

extern "C" void kernel_launch(void* const* d_in, const int* in_sizes, int n_in,
                              void* d_out, int out_size)
{
    (void)in_sizes; (void)n_in; (void)out_size;
    const float* x  = (const float*)d_in[0];
    const float* W0 = (const float*)d_in[1];
    const float* b0 = (const float*)d_in[2];
    const float* W1 = (const float*)d_in[3];
    const float* b1 = (const float*)d_in[4];

    lstm_rearrange<<<4096, 256>>>(W0, W1);

    cudaFuncSetAttribute(lstm_persist,
                         cudaFuncAttributeMaxDynamicSharedMemorySize, SMEM_BYTES);
    lstm_persist<<<NCTA, NTHR, SMEM_BYTES>>>(x, b0, b1, (float*)d_out);
}

// round 6
// speedup vs baseline: 1.8984x; 1.4409x over previous
#include <cuda_runtime.h>
#include <cstdint>
#include <cstddef>

// ---------------------------------------------------------------------------
// 2-layer LSTM, B=32, T=512, I=H=1024, fp32 — wavefront-pipelined layers.
//
// CTAs 0..63  = group A: layer 0 at time t=s      (active s < 512)
// CTAs 64..127= group B: layer 1 at time t=s-1    (active s >= 1)
// 513 wavefront steps, one grid barrier each. Per step each CTA does
// 64 gate-rows x 32 batches x k=2048:
//   - 16 k-stages of 128, cp.async 4-deep pipeline, ONE __syncthreads/stage
//   - 8 warps: 2-way k-split x 4 row-blocks; thread tile 4 rows x 4 batches
//     -> 32 FFMA2 (fma.rn.f32x2) per 8 LDS.128, all smem loads conflict-free
//   - weights pre-rearranged once into per-(cta,stage) contiguous swizzled
//     blocks; c-state in registers for all 512 steps
// ---------------------------------------------------------------------------

#define NCTA   128
#define NTHR   256
#define TSTEPS 512
#define HDIM   1024

#define OFF_W   0u         // 4 x 32KB weight stage buffers
#define OFF_C   131072u    // 4 x 16KB comb stage buffers
#define OFF_GS  196608u    // 64x33 floats gate results
#define SMEM_BYTES (196608 + 64 * 33 * 4)   // 205056

// rearranged weights: [l][cta64][stage16][2048 float4] (row/kq swizzled)
__device__ __align__(16) float g_Wre[2u * 64u * 16u * 2048u * 4u];
// h ping-pong: [layer][pp][b*1024+n]
__device__ __align__(16) float g_h[2 * 2 * 32 * HDIM];
__device__ unsigned g_bar_count;
__device__ volatile unsigned g_bar_gen;

union F2 { unsigned long long u; float2 f; };

__device__ __forceinline__ void ffma2(unsigned long long& acc,
                                      unsigned long long a,
                                      unsigned long long b) {
    asm volatile("fma.rn.f32x2 %0, %1, %2, %0;" : "+l"(acc) : "l"(a), "l"(b));
}
__device__ __forceinline__ void cpa16(uint32_t dst, const void* src) {
    asm volatile("cp.async.cg.shared.global [%0], [%1], 16;" :: "r"(dst), "l"(src));
}
__device__ __forceinline__ void cp_commit() {
    asm volatile("cp.async.commit_group;");
}
template<int N> __device__ __forceinline__ void cp_wait() {
    asm volatile("cp.async.wait_group %0;" :: "n"(N));
}

__device__ __forceinline__ void grid_bar() {
    __syncthreads();
    if (threadIdx.x == 0) {
        __threadfence();
        unsigned gen = g_bar_gen;
        if (atomicAdd(&g_bar_count, 1u) == NCTA - 1) {
            g_bar_count = 0;
            __threadfence();
            g_bar_gen = gen + 1;
        } else {
            while (g_bar_gen == gen) { __nanosleep(32); }
        }
        __threadfence();
    }
    __syncthreads();
}

// stage weights: contiguous pre-swizzled 32KB block -> smem buffer
__device__ __forceinline__ void fetch_W(uint32_t sb, uint32_t dstoff,
                                        int l, int gcta, int s, int tid) {
    const float4* src = ((const float4*)g_Wre) +
                        (((size_t)l * 64 + gcta) * 16 + s) * 2048;
    uint32_t d = sb + OFF_W + dstoff;
    #pragma unroll
    for (int i = 0; i < 8; i++) {
        int m = tid + i * 256;
        cpa16(d + m * 16, src + m);
    }
}

// stage activations: 32 b x 128 k, swizzled slot c holds kq = c ^ (b>>2)
__device__ __forceinline__ void fetch_C(uint32_t sb, uint32_t dstoff,
                                        const float* base, size_t stride,
                                        int tid) {
    uint32_t d = sb + OFF_C + dstoff;
    #pragma unroll
    for (int i = 0; i < 4; i++) {
        int m = tid + i * 256;
        int b = m >> 5, c = m & 31;
        cpa16(d + m * 16,
              base + (size_t)b * stride + ((c ^ (b >> 2)) << 2));
    }
}

// one-time weight rearrangement
extern "C" __global__ void lstm_rearrange(const float* __restrict__ W0,
                                          const float* __restrict__ W1) {
    unsigned gid = blockIdx.x * 256u + threadIdx.x;
    #pragma unroll
    for (int i = 0; i < 4; i++) {
        unsigned m   = gid + (unsigned)i * 1048576u;
        unsigned c   = m & 31u;
        unsigned r   = (m >> 5) & 63u;
        unsigned s   = (m >> 11) & 15u;
        unsigned cta = (m >> 15) & 63u;
        unsigned l   = m >> 21;
        unsigned sw  = ((r >> 2) & 3u) * 2u;
        unsigned gr  = (r >> 4) * 1024u + cta * 16u + (r & 15u);
        const float* W = l ? W1 : W0;
        ((float4*)g_Wre)[m] =
            ((const float4*)W)[(size_t)gr * 512 + s * 32 + (c ^ sw)];
    }
}

extern "C" __global__ void __launch_bounds__(NTHR, 1)
lstm_persist(const float* __restrict__ x,
             const float* __restrict__ b0,
             const float* __restrict__ b1,
             float* __restrict__ out)
{
    extern __shared__ char sm[];
    const uint32_t sb = (uint32_t)__cvta_generic_to_shared(sm);
    float* gs = (float*)(sm + OFF_GS);

    const int tid   = threadIdx.x;
    const int cta   = blockIdx.x;
    const int gsel  = cta >> 6;         // 0 = layer0 (A), 1 = layer1 (B)
    const int gcta  = cta & 63;
    const int w     = tid >> 5;
    const int lane  = tid & 31;
    const int khalf = w >> 2;           // 0/1: kq-half within stage
    const int rblk  = w & 3;            // 4 row-blocks of 16 rows
    const int rlane = lane >> 3;        // 0..3
    const int blane = lane & 7;         // 0..7
    const int rbase = rblk * 16 + rlane * 4;   // first of thread's 4 rows
    const int wsw   = rlane * 2;        // W kq swizzle for this thread

    // pointwise: 2 items per thread: (neuron nj, batch pb)
    const int nj0 = tid & 15, pb0 = tid >> 4;          // item 0
    const int nj1 = nj0, pb1 = pb0 + 16;               // item 1 (tid+256)

    // zero h state
    {
        int base = cta * 1024 + tid;
        #pragma unroll
        for (int k = 0; k < 4; k++) g_h[base + k * 256] = 0.f;
    }

    const float* bias = gsel ? b1 : b0;
    float br0[4], br1[4];
    #pragma unroll
    for (int g = 0; g < 4; ++g) {
        br0[g] = bias[g * HDIM + gcta * 16 + nj0];
        br1[g] = bias[g * HDIM + gcta * 16 + nj1];
    }
    float cst0 = 0.f, cst1 = 0.f;

    grid_bar();

    #pragma unroll 1
    for (int s = 0; s <= TSTEPS; ++s) {
        const bool active = gsel ? (s >= 1) : (s < TSTEPS);
        const int  t      = gsel ? (s - 1) : s;          // my time index
        const int  pprev  = (s + 1) & 1;                 // h0(s-1) parity

        if (active) {
            // ---- stage source resolver ----
            auto src_of = [&](int st, const float*& base, size_t& stride) {
                if (gsel == 0) {
                    if (st < 8) { base = x + (size_t)t * 1024 + st * 128; stride = 524288; }
                    else        { base = g_h + pprev * 32768 + (st - 8) * 128; stride = 1024; }
                } else {
                    if (st < 8) { base = g_h + pprev * 32768 + st * 128; stride = 1024; }
                    else        { base = g_h + (2 + (s & 1)) * 32768 + (st - 8) * 128; stride = 1024; }
                }
            };

            // ---- bootstrap pipeline: stages 0,1 ----
            {
                const float* cb; size_t cs;
                fetch_W(sb, 0u, gsel, gcta, 0, tid);
                src_of(0, cb, cs); fetch_C(sb, 0u, cb, cs, tid);
                cp_commit();
                fetch_W(sb, 32768u, gsel, gcta, 1, tid);
                src_of(1, cb, cs); fetch_C(sb, 16384u, cb, cs, tid);
                cp_commit();
            }

            unsigned long long acc[32];
            #pragma unroll
            for (int i = 0; i < 32; i++) acc[i] = 0ull;

            #pragma unroll 1
            for (int st = 0; st < 16; ++st) {
                if (st + 2 < 16) {
                    const int nf = st + 2;
                    fetch_W(sb, (uint32_t)((nf & 3) << 15), gsel, gcta, nf, tid);
                    const float* cb; size_t cs;
                    src_of(nf, cb, cs);
                    fetch_C(sb, (uint32_t)((nf & 3) << 14), cb, cs, tid);
                }
                cp_commit();
                cp_wait<2>();
                __syncthreads();

                const char* Wp = sm + ((st & 3) << 15) + rbase * 512;
                const char* Cp = sm + OFF_C + ((st & 3) << 14) + blane * 2048;
                const int kq0 = khalf * 16;
                #pragma unroll 4
                for (int kq = kq0; kq < kq0 + 16; ++kq) {
                    const int wo = (kq ^ wsw)   << 4;
                    const int co = (kq ^ blane) << 4;
                    ulonglong2 wv0 = *(const ulonglong2*)(Wp + wo);
                    ulonglong2 wv1 = *(const ulonglong2*)(Wp + wo + 512);
                    ulonglong2 wv2 = *(const ulonglong2*)(Wp + wo + 1024);
                    ulonglong2 wv3 = *(const ulonglong2*)(Wp + wo + 1536);
                    ulonglong2 cv0 = *(const ulonglong2*)(Cp + co);
                    ulonglong2 cv1 = *(const ulonglong2*)(Cp + co + 512);
                    ulonglong2 cv2 = *(const ulonglong2*)(Cp + co + 1024);
                    ulonglong2 cv3 = *(const ulonglong2*)(Cp + co + 1536);
                    ffma2(acc[0],  wv0.x, cv0.x); ffma2(acc[1],  wv0.y, cv0.y);
                    ffma2(acc[2],  wv0.x, cv1.x); ffma2(acc[3],  wv0.y, cv1.y);
                    ffma2(acc[4],  wv0.x, cv2.x); ffma2(acc[5],  wv0.y, cv2.y);
                    ffma2(acc[6],  wv0.x, cv3.x); ffma2(acc[7],  wv0.y, cv3.y);
                    ffma2(acc[8],  wv1.x, cv0.x); ffma2(acc[9],  wv1.y, cv0.y);
                    ffma2(acc[10], wv1.x, cv1.x); ffma2(acc[11], wv1.y, cv1.y);
                    ffma2(acc[12], wv1.x, cv2.x); ffma2(acc[13], wv1.y, cv2.y);
                    ffma2(acc[14], wv1.x, cv3.x); ffma2(acc[15], wv1.y, cv3.y);
                    ffma2(acc[16], wv2.x, cv0.x); ffma2(acc[17], wv2.y, cv0.y);
                    ffma2(acc[18], wv2.x, cv1.x); ffma2(acc[19], wv2.y, cv1.y);
                    ffma2(acc[20], wv2.x, cv2.x); ffma2(acc[21], wv2.y, cv2.y);
                    ffma2(acc[22], wv2.x, cv3.x); ffma2(acc[23], wv2.y, cv3.y);
                    ffma2(acc[24], wv3.x, cv0.x); ffma2(acc[25], wv3.y, cv0.y);
                    ffma2(acc[26], wv3.x, cv1.x); ffma2(acc[27], wv3.y, cv1.y);
                    ffma2(acc[28], wv3.x, cv2.x); ffma2(acc[29], wv3.y, cv2.y);
                    ffma2(acc[30], wv3.x, cv3.x); ffma2(acc[31], wv3.y, cv3.y);
                }
                __syncthreads();
            }

            // ---- k-split reduction into gs[64][33] ----
            if (khalf == 0) {
                #pragma unroll
                for (int j = 0; j < 4; j++)
                    #pragma unroll
                    for (int bt = 0; bt < 4; bt++) {
                        F2 u0, u1;
                        u0.u = acc[j * 8 + bt * 2 + 0];
                        u1.u = acc[j * 8 + bt * 2 + 1];
                        gs[(rbase + j) * 33 + blane * 4 + bt] =
                            u0.f.x + u0.f.y + u1.f.x + u1.f.y;
                    }
            }
            __syncthreads();
            if (khalf == 1) {
                #pragma unroll
                for (int j = 0; j < 4; j++)
                    #pragma unroll
                    for (int bt = 0; bt < 4; bt++) {
                        F2 u0, u1;
                        u0.u = acc[j * 8 + bt * 2 + 0];
                        u1.u = acc[j * 8 + bt * 2 + 1];
                        gs[(rbase + j) * 33 + blane * 4 + bt] +=
                            u0.f.x + u0.f.y + u1.f.x + u1.f.y;
                    }
            }
            __syncthreads();

            // ---- pointwise, 2 items ----
            const int wp = gsel ? ((s + 1) & 1) : (s & 1);   // write parity
            #pragma unroll
            for (int it = 0; it < 2; ++it) {
                const int nj = it ? nj1 : nj0;
                const int pb = it ? pb1 : pb0;
                const float* brp = it ? br1 : br0;
                float fg = gs[(0  + nj) * 33 + pb] + brp[0];
                float ig = gs[(16 + nj) * 33 + pb] + brp[1];
                float gg = gs[(32 + nj) * 33 + pb] + brp[2];
                float og = gs[(48 + nj) * 33 + pb] + brp[3];
                fg = 1.f / (1.f + expf(-fg));
                ig = 1.f / (1.f + expf(-ig));
                og = 1.f / (1.f + expf(-og));
                float cprev = it ? cst1 : cst0;
                float c = fg * cprev + ig * tanhf(gg);
                if (it) cst1 = c; else cst0 = c;
                float h = og * tanhf(c);

                const int n = gcta * 16 + nj;
                g_h[(gsel * 2 + wp) * 32768 + pb * HDIM + n] = h;
                if (gsel == 1)
                    out[(size_t)pb * 524288 + (size_t)t * 1024 + n] = h;
                if (t == TSTEPS - 1) {
                    out[16777216 + gsel * 32768 + pb * 1024 + n] = h;   // h_n
                    out[16842752 + gsel * 32768 + pb * 1024 + n] = c;   // c_n
                }
            }
        }

        grid_bar();
    }
}

extern "C" void kernel_launch(void* const* d_in, const int* in_sizes, int n_in,
                              void* d_out, int out_size)
{
    (void)in_sizes; (void)n_in; (void)out_size;
    const float* x  = (const float*)d_in[0];
    const float* W0 = (const float*)d_in[1];
    const float* b0 = (const float*)d_in[2];
    const float* W1 = (const float*)d_in[3];
    const float* b1 = (const float*)d_in[4];

    lstm_rearrange<<<4096, 256>>>(W0, W1);

    cudaFuncSetAttribute(lstm_persist,
                         cudaFuncAttributeMaxDynamicSharedMemorySize, SMEM_BYTES);
    lstm_persist<<<NCTA, NTHR, SMEM_BYTES>>>(x, b0, b1, (float*)d_out);
}